// round 1
// baseline (speedup 1.0000x reference)
#include <cuda_runtime.h>

// FlowNetC correlation on GB300.
// out[b, dy*21+dx, y, x] = (1/256) * sum_c in1[b,c,y,x] * in2[b,c, y+2dy-20, x+2dx-20]
// (zero outside bounds).
//
// Block = (dy-group of 7, y, b). 7 warps, one warp per dy.
// Parity de-interleaved smem: stride-2 displacement means out[x,*] only reads
// in2 columns of x's parity -> thread owns 4 same-parity x * 21 dx = 84 accs,
// per channel: 7x LDS.128 feed 84 FFMAs.

#define NW        7          // dy values (warps) per block
#define CK        8          // channels per smem chunk
#define NTHREADS  (NW * 32)  // 224
#define C_TOT     256
#define NCHUNK    (C_TOT / CK)
#define H         96
#define W         128
#define DD        21

struct __align__(16) Smem {
    float in2s[NW][CK][2][84];   // [dy][c][parity][padded deint cols] 37632 B
    float in1s[CK][2][64];       //                                     4096 B
    float stage[NW][128];        // output transpose staging            3584 B
};                               // total 45312 B (< 48KB static)

__global__ void __launch_bounds__(NTHREADS) corr_kernel(
    const float* __restrict__ g_in1,
    const float* __restrict__ g_in2,
    float*       __restrict__ g_out)
{
    __shared__ Smem sm;

    const int b    = blockIdx.z;
    const int y    = blockIdx.y;
    const int dyg  = blockIdx.x;          // 0..2
    const int tid  = threadIdx.x;
    const int w    = tid >> 5;            // warp = local dy
    const int lane = tid & 31;
    const int p    = lane >> 4;           // parity
    const int g    = lane & 15;
    const int U    = g << 2;              // base deint index (multiple of 4)
    const int dy0  = dyg * NW;

    // Zero the x-pad regions (u in [0,10) and [74,84)) once. The interior
    // [10,74) is fully rewritten every chunk; pads stay zero.
    for (int e = tid; e < NW * CK * 2 * 20; e += NTHREADS) {
        int u = e % 20; u = (u < 10) ? u : (u + 64);
        int rest = e / 20;
        int pp = rest & 1;
        int cc = (rest >> 1) & (CK - 1);
        int ww = rest >> 4;
        sm.in2s[ww][cc][pp][u] = 0.0f;
    }

    const size_t plane = (size_t)H * W;
    const float* in1b = g_in1 + ((size_t)b * C_TOT) * plane + (size_t)y * W;
    const float* in2b = g_in2 + ((size_t)b * C_TOT) * plane;

    float acc[4][21];
    #pragma unroll
    for (int i = 0; i < 4; ++i) {
        #pragma unroll
        for (int j = 0; j < 21; ++j) acc[i][j] = 0.0f;
    }

    // ---- loader coordinate decode (loop-invariant) ----
    // in2: 1792 float4s per chunk; e4 = q*224 + tid
    int  l_off[8];   // element offset within (c-plane): row2*W + col4*4
    int  l_cc[8];
    bool l_ok[8];
    #pragma unroll
    for (int q = 0; q < 8; ++q) {
        int e4   = q * NTHREADS + tid;
        int col4 = e4 & 31;
        l_cc[q]  = (e4 >> 5) & 7;
        int ww   = e4 >> 8;                 // 0..6
        int row2 = y + 2 * (dy0 + ww) - 20; // [-20, 115]
        l_ok[q]  = (row2 >= 0) && (row2 < H);
        l_off[q] = row2 * W + col4 * 4;
    }
    const int i1_col4 = tid & 31;
    const int i1_cc   = tid >> 5;           // 0..6; cc=7 handled by tid<32

    float4 pf2[8];
    float4 pf1a, pf1b;

    // prefetch chunk 0
    {
        #pragma unroll
        for (int q = 0; q < 8; ++q)
            pf2[q] = l_ok[q]
                ? *(const float4*)(in2b + (size_t)l_cc[q] * plane + l_off[q])
                : make_float4(0.f, 0.f, 0.f, 0.f);
        pf1a = *(const float4*)(in1b + (size_t)i1_cc * plane + i1_col4 * 4);
        if (tid < 32)
            pf1b = *(const float4*)(in1b + (size_t)7 * plane + tid * 4);
    }

    for (int k = 0; k < NCHUNK; ++k) {
        __syncthreads();  // everyone done reading smem from previous chunk

        // store prefetched chunk, de-interleaving by parity.
        // float4 = cols 4c..4c+3 -> even pair {x,z} at u=2c+10, odd pair {y,w}.
        #pragma unroll
        for (int q = 0; q < 8; ++q) {
            int e4   = q * NTHREADS + tid;
            int col4 = e4 & 31;
            int cc   = (e4 >> 5) & 7;
            int ww   = e4 >> 8;
            *(float2*)&sm.in2s[ww][cc][0][2 * col4 + 10] = make_float2(pf2[q].x, pf2[q].z);
            *(float2*)&sm.in2s[ww][cc][1][2 * col4 + 10] = make_float2(pf2[q].y, pf2[q].w);
        }
        *(float2*)&sm.in1s[i1_cc][0][2 * i1_col4] = make_float2(pf1a.x, pf1a.z);
        *(float2*)&sm.in1s[i1_cc][1][2 * i1_col4] = make_float2(pf1a.y, pf1a.w);
        if (tid < 32) {
            *(float2*)&sm.in1s[7][0][2 * tid] = make_float2(pf1b.x, pf1b.z);
            *(float2*)&sm.in1s[7][1][2 * tid] = make_float2(pf1b.y, pf1b.w);
        }
        __syncthreads();  // smem ready

        // prefetch chunk k+1 (latency hidden under compute below)
        if (k + 1 < NCHUNK) {
            const size_t cbase = (size_t)(k + 1) * CK * plane;
            #pragma unroll
            for (int q = 0; q < 8; ++q)
                pf2[q] = l_ok[q]
                    ? *(const float4*)(in2b + cbase + (size_t)l_cc[q] * plane + l_off[q])
                    : make_float4(0.f, 0.f, 0.f, 0.f);
            pf1a = *(const float4*)(in1b + cbase + (size_t)i1_cc * plane + i1_col4 * 4);
            if (tid < 32)
                pf1b = *(const float4*)(in1b + cbase + (size_t)7 * plane + tid * 4);
        }

        // ---- compute chunk k: per channel 7x LDS.128 -> 84 FFMA ----
        #pragma unroll
        for (int cc = 0; cc < CK; ++cc) {
            float4 av = *(const float4*)&sm.in1s[cc][p][U];
            float a0 = av.x, a1 = av.y, a2 = av.z, a3 = av.w;
            float r[24];
            #pragma unroll
            for (int q = 0; q < 6; ++q)
                *(float4*)&r[4 * q] = *(const float4*)&sm.in2s[w][cc][p][U + 4 * q];
            #pragma unroll
            for (int j = 0; j < 21; ++j) {
                acc[0][j] = fmaf(a0, r[j + 0], acc[0][j]);
                acc[1][j] = fmaf(a1, r[j + 1], acc[1][j]);
                acc[2][j] = fmaf(a2, r[j + 2], acc[2][j]);
                acc[3][j] = fmaf(a3, r[j + 3], acc[3][j]);
            }
        }
    }

    // ---- epilogue: smem transpose -> fully coalesced 512B row stores ----
    const float scale = 1.0f / 256.0f;
    const int   dy    = dy0 + w;
    float* outb = g_out + (((size_t)b * (DD * DD)) * H + y) * W;
    #pragma unroll
    for (int j = 0; j < 21; ++j) {
        #pragma unroll
        for (int i = 0; i < 4; ++i)
            sm.stage[w][2 * (U + i) + p] = acc[i][j] * scale;
        __syncwarp();
        float4 v = *(const float4*)&sm.stage[w][lane * 4];
        *(float4*)(outb + (size_t)(dy * DD + j) * plane + lane * 4) = v;
        __syncwarp();
    }
}

extern "C" void kernel_launch(void* const* d_in, const int* in_sizes, int n_in,
                              void* d_out, int out_size)
{
    (void)in_sizes; (void)n_in; (void)out_size;
    const float* in1 = (const float*)d_in[0];
    const float* in2 = (const float*)d_in[1];
    float*       out = (float*)d_out;

    dim3 grid(3, H, 8);      // (dy-group, y, b) -> 2304 blocks
    dim3 block(NTHREADS);    // 224 = 7 warps
    corr_kernel<<<grid, block>>>(in1, in2, out);
}